// round 15
// baseline (speedup 1.0000x reference)
#include <cuda_runtime.h>
#include <cuda_fp16.h>
#include <math.h>
#include <stdint.h>

#define TDIM 2048
#define CDIM 1024
#define HN   8
#define NW   8192
#define WIN  256
#define KQ   320
#define TT   64
#define NTIL 32
#define GAMMA 0.96875f

// fp16 operands, all single precision.
__device__ __half g_Xh[(size_t)TDIM * CDIM];
__device__ __half g_Wth[(size_t)3 * NW * CDIM];            // [z][n][k]
__device__ __half g_Qh[(size_t)HN * TDIM * CDIM];
__device__ __half g_Kh[(size_t)HN * TDIM * CDIM];
__device__ __half g_Vh[(size_t)HN * TDIM * CDIM];          // [h][t][c]
__device__ __half g_Vth[(size_t)HN * CDIM * TDIM];         // [h][c][t]
__device__ __half g_Ph[(size_t)HN * NTIL * TT * KQ];       // [h][tile][t][q]

// ---------------------------------------------------------------------------
#define CP16(dst, src) \
    asm volatile("cp.async.cg.shared.global [%0], [%1], 16;" :: "r"(dst), "l"(src))
#define CP16Z(dst, src, sz) \
    asm volatile("cp.async.cg.shared.global [%0], [%1], 16, %2;" :: "r"(dst), "l"(src), "r"(sz))
#define CP_COMMIT() asm volatile("cp.async.commit_group;" ::: "memory")
#define CP_WAIT1()  asm volatile("cp.async.wait_group 1;" ::: "memory")
#define CP_WAIT0()  asm volatile("cp.async.wait_group 0;" ::: "memory")

__device__ __forceinline__ uint32_t smem_u32(const void* p) {
    uint32_t a;
    asm("{ .reg .u64 t; cvta.to.shared.u64 t, %1; cvt.u32.u64 %0, t; }"
        : "=r"(a) : "l"(p));
    return a;
}

__device__ __forceinline__ void mma_f16(float c[4], const uint32_t a[4],
                                        const uint32_t b[2]) {
    asm volatile(
        "mma.sync.aligned.m16n8k16.row.col.f32.f16.f16.f32 "
        "{%0,%1,%2,%3}, {%4,%5,%6,%7}, {%8,%9}, {%0,%1,%2,%3};"
        : "+f"(c[0]), "+f"(c[1]), "+f"(c[2]), "+f"(c[3])
        : "r"(a[0]), "r"(a[1]), "r"(a[2]), "r"(a[3]), "r"(b[0]), "r"(b[1]));
}

__device__ __forceinline__ uint32_t pack_h2(float v0, float v1) {
    __half2 h = __floats2half2_rn(v0, v1);
    return *(uint32_t*)&h;
}

// ---------------------------------------------------------------------------
// Prep: X -> fp16
// ---------------------------------------------------------------------------
__global__ __launch_bounds__(256) void prep_x(const float* __restrict__ X)
{
    int i = blockIdx.x * 256 + threadIdx.x;
    float4 v = ((const float4*)X)[i];
    ((uint2*)g_Xh)[i] = make_uint2(pack_h2(v.x, v.y), pack_h2(v.z, v.w));
}

// ---------------------------------------------------------------------------
// Prep: transpose W [K,N] -> Wt [N,K], fp16
// ---------------------------------------------------------------------------
__global__ __launch_bounds__(256) void prep_w(
    const float* __restrict__ Wq, const float* __restrict__ Wk,
    const float* __restrict__ Wv)
{
    const int z = blockIdx.z;
    const float* W = (z == 0) ? Wq : ((z == 1) ? Wk : Wv);
    const int n0 = blockIdx.x * 32;
    const int k0 = blockIdx.y * 32;

    __shared__ float t[32][33];
    const int tx = threadIdx.x, ty = threadIdx.y;
#pragma unroll
    for (int j = 0; j < 4; j++)
        t[ty + 8 * j][tx] = W[(size_t)(k0 + ty + 8 * j) * NW + n0 + tx];
    __syncthreads();
#pragma unroll
    for (int j = 0; j < 4; j++) {
        float v = t[tx][ty + 8 * j];
        size_t o = ((size_t)z * NW + n0 + ty + 8 * j) * CDIM + k0 + tx;
        g_Wth[o] = __float2half_rn(v);
    }
}

// ---------------------------------------------------------------------------
// Projection: single-term fp16, fused RoPE+SiLU, outputs Q/K/V fp16.
// (Round-10/12 exact shape — occ-2 is load-bearing.)
// ---------------------------------------------------------------------------
#define PSTAGE 20480
#define SMEM_PROJ (3 * PSTAGE)

__device__ __forceinline__ void proj_load_stage(
    uint32_t stb, int tid, int m0, int zn0, int k0)
{
#pragma unroll
    for (int i = 0; i < 4; i++) {
        const int c = tid + i * 256;
        if (c < 512) {
            const int row = c >> 2;
            const int ch  = c & 3;
            const __half* src = g_Xh + (size_t)(m0 + row) * CDIM + k0 + ch * 8;
            CP16(stb + row * 80 + ch * 16, src);
        } else {
            const int rem = c - 512;
            const int row = rem >> 2;
            const int ch  = rem & 3;
            const __half* src = g_Wth + (size_t)(zn0 + row) * CDIM + k0 + ch * 8;
            CP16(stb + 10240 + row * 80 + ch * 16, src);
        }
    }
}

__global__ __launch_bounds__(256, 2) void proj_mma()
{
    extern __shared__ char smem[];
    const uint32_t sb = smem_u32(smem);
    const int tid = threadIdx.x;
    const int wid = tid >> 5;
    const int lane = tid & 31;
    const int wm = wid & 1, wn = wid >> 1;
    const int g = lane >> 2, t4 = lane & 3;

    const int m0 = blockIdx.x * 128;
    const int n0 = blockIdx.y * 128;
    const int z  = blockIdx.z;
    const int zn0 = z * NW + n0;

    float acc[4][4][4];
#pragma unroll
    for (int i = 0; i < 4; i++)
#pragma unroll
        for (int j = 0; j < 4; j++)
#pragma unroll
            for (int q = 0; q < 4; q++) acc[i][j][q] = 0.f;

    proj_load_stage(sb, tid, m0, zn0, 0);
    CP_COMMIT();
    proj_load_stage(sb + PSTAGE, tid, m0, zn0, 32);
    CP_COMMIT();

#pragma unroll 1
    for (int s = 0; s < 32; s++) {
        if (s < 31) { CP_WAIT1(); } else { CP_WAIT0(); }
        __syncthreads();
        if (s + 2 < 32) {
            proj_load_stage(sb + ((s + 2) % 3) * PSTAGE, tid, m0, zn0, (s + 2) * 32);
            CP_COMMIT();
        }
        const char* st = smem + (s % 3) * PSTAGE;
        const char* Ah = st;
        const char* Bh = st + 10240;

#pragma unroll
        for (int kk = 0; kk < 32; kk += 16) {
            uint32_t ah[4][4];
#pragma unroll
            for (int i = 0; i < 4; i++) {
                const int b0 = (wm * 64 + i * 16 + g) * 80 + kk * 2 + t4 * 4;
                ah[i][0] = *(const uint32_t*)(Ah + b0);
                ah[i][1] = *(const uint32_t*)(Ah + b0 + 640);
                ah[i][2] = *(const uint32_t*)(Ah + b0 + 16);
                ah[i][3] = *(const uint32_t*)(Ah + b0 + 656);
            }
            uint32_t bh[4][2];
#pragma unroll
            for (int j = 0; j < 4; j++) {
                const int bb = (wn * 32 + j * 8 + g) * 80 + kk * 2 + t4 * 4;
                bh[j][0] = *(const uint32_t*)(Bh + bb);
                bh[j][1] = *(const uint32_t*)(Bh + bb + 16);
            }
#pragma unroll
            for (int i = 0; i < 4; i++)
#pragma unroll
                for (int j = 0; j < 4; j++)
                    mma_f16(acc[i][j], ah[i], bh[j]);
        }
    }

    // epilogue: RoPE (Q,K cols<64) + SiLU, fp16 store
    const int h  = n0 >> 10;
    const int cbase = (n0 & 1023) + wn * 32 + 2 * t4;
    const bool rope_blk = (z < 2) && ((n0 & 1023) == 0) && (wn < 2);

    __half* Hi = (z == 0) ? g_Qh : ((z == 1) ? g_Kh : g_Vh);
    Hi += (size_t)h * TDIM * CDIM;

#pragma unroll
    for (int i = 0; i < 4; i++) {
#pragma unroll
        for (int rr = 0; rr < 2; rr++) {
            const int r = m0 + wm * 64 + i * 16 + g + rr * 8;
#pragma unroll
            for (int j = 0; j < 4; j++) {
                const int col = cbase + j * 8;
                float v0 = acc[i][j][2 * rr];
                float v1 = acc[i][j][2 * rr + 1];
                if (rope_blk) {
                    int c2 = col >> 1;
                    float invf = (float)exp(-((double)(2 * c2) / 64.0) * log(10000.0));
                    float ang = (float)r * invf;
                    float sn, cs;
                    sincosf(ang, &sn, &cs);
                    float y0 = v0 * cs - v1 * sn;
                    float y1 = v1 * cs + v0 * sn;
                    v0 = y0; v1 = y1;
                }
                v0 = v0 / (1.f + expf(-v0));
                v1 = v1 / (1.f + expf(-v1));
                ((uint32_t*)Hi)[((size_t)r * CDIM + col) >> 1] = pack_h2(v0, v1);
            }
        }
    }
}

// ---------------------------------------------------------------------------
// V transpose: [h][t][c] -> [h][c][t], vectorized (16B global accesses).
// Block: 64 t x 64 c, 256 threads.
// ---------------------------------------------------------------------------
__global__ __launch_bounds__(256) void transpose_v()
{
    __shared__ unsigned short sm[64][72];   // [c][t], 144B row stride (16B-aligned)
    const int c0 = blockIdx.x * 64;
    const int t0 = blockIdx.y * 64;
    const int h  = blockIdx.z;
    const int tid = threadIdx.x;

    const unsigned short* Vh = (const unsigned short*)g_Vh + (size_t)h * TDIM * CDIM;
    {
        const int tl = tid >> 2;           // 0..63
        const int ck = (tid & 3) * 16;     // 0,16,32,48
        uint4 v0 = *(const uint4*)(Vh + (size_t)(t0 + tl) * CDIM + c0 + ck);
        uint4 v1 = *(const uint4*)(Vh + (size_t)(t0 + tl) * CDIM + c0 + ck + 8);
        const unsigned short* p0 = (const unsigned short*)&v0;
        const unsigned short* p1 = (const unsigned short*)&v1;
#pragma unroll
        for (int k = 0; k < 8; k++) {
            sm[ck + k][tl]     = p0[k];
            sm[ck + 8 + k][tl] = p1[k];
        }
    }
    __syncthreads();
    {
        const int cl = tid >> 2;           // 0..63
        const int tk = (tid & 3) * 16;     // 0,16,32,48
        unsigned short* dst = (unsigned short*)g_Vth
            + ((size_t)h * CDIM + c0 + cl) * TDIM + t0 + tk;
        *(uint4*)(dst)     = *(const uint4*)(&sm[cl][tk]);
        *(uint4*)(dst + 8) = *(const uint4*)(&sm[cl][tk + 8]);
    }
}

// ---------------------------------------------------------------------------
// qk_mma: P = decay * (K Q^T), single-term fp16, Kstage=64.  (R14 shape.)
// ---------------------------------------------------------------------------
#define QKSTAGE 32256
#define SMEM_QK (3 * QKSTAGE)

__global__ __launch_bounds__(256, 2) void qk_mma()
{
    extern __shared__ char smem[];
    const uint32_t sb = smem_u32(smem);
    const int tid = threadIdx.x;
    const int wid = tid >> 5;
    const int lane = tid & 31;
    const int wm = wid & 1, wn = wid >> 1;
    const int g = lane >> 2, t4 = lane & 3;

    const int qc   = blockIdx.x;          // 0..1
    const int tile = blockIdx.y;
    const int h    = blockIdx.z;
    const int t0   = tile * TT;
    const int q0   = t0 + qc * 160;

    const __half* Kh = g_Kh + (size_t)h * TDIM * CDIM;
    const __half* Qh = g_Qh + (size_t)h * TDIM * CDIM;

    float acc[2][5][4];
#pragma unroll
    for (int i = 0; i < 2; i++)
#pragma unroll
        for (int j = 0; j < 5; j++)
#pragma unroll
            for (int q = 0; q < 4; q++) acc[i][j][q] = 0.f;

    auto load_stage = [&](int s, uint32_t stb) {
        const int k0 = s * 64;
#pragma unroll
        for (int i = 0; i < 7; i++) {
            const int c = tid + i * 256;
            if (c < 512) {
                const int row = c >> 3, ch = c & 7;
                const __half* src = Kh + (size_t)(t0 + row) * CDIM + k0 + ch * 8;
                CP16(stb + row * 144 + ch * 16, src);
            } else {
                const int rem = c - 512;
                const int row = rem >> 3, ch = rem & 7;
                int q = q0 + row;
                int sz = (q < TDIM) ? 16 : 0;
                if (q >= TDIM) q = 0;
                const __half* src = Qh + (size_t)q * CDIM + k0 + ch * 8;
                CP16Z(stb + 9216 + row * 144 + ch * 16, src, sz);
            }
        }
    };

    load_stage(0, sb);
    CP_COMMIT();
    load_stage(1, sb + QKSTAGE);
    CP_COMMIT();

#pragma unroll 1
    for (int s = 0; s < 16; s++) {
        if (s < 15) { CP_WAIT1(); } else { CP_WAIT0(); }
        __syncthreads();
        if (s + 2 < 16) {
            load_stage(s + 2, sb + ((s + 2) % 3) * QKSTAGE);
            CP_COMMIT();
        }
        const char* st = smem + (s % 3) * QKSTAGE;
        const char* Ah = st;
        const char* Bh = st + 9216;

#pragma unroll
        for (int kk = 0; kk < 64; kk += 16) {
            uint32_t ah[2][4];
#pragma unroll
            for (int i = 0; i < 2; i++) {
                const int b0 = (wm * 32 + i * 16 + g) * 144 + kk * 2 + t4 * 4;
                ah[i][0] = *(const uint32_t*)(Ah + b0);
                ah[i][1] = *(const uint32_t*)(Ah + b0 + 1152);
                ah[i][2] = *(const uint32_t*)(Ah + b0 + 16);
                ah[i][3] = *(const uint32_t*)(Ah + b0 + 1168);
            }
            uint32_t bh[5][2];
#pragma unroll
            for (int j = 0; j < 5; j++) {
                const int bb = (wn * 40 + j * 8 + g) * 144 + kk * 2 + t4 * 4;
                bh[j][0] = *(const uint32_t*)(Bh + bb);
                bh[j][1] = *(const uint32_t*)(Bh + bb + 16);
            }
#pragma unroll
            for (int i = 0; i < 2; i++)
#pragma unroll
                for (int j = 0; j < 5; j++)
                    mma_f16(acc[i][j], ah[i], bh[j]);
        }
    }

    // epilogue: decay + mask, fp16 store P
    const float lg = log2f(GAMMA);
    __half* Phb = g_Ph + ((size_t)h * NTIL + tile) * TT * KQ;
#pragma unroll
    for (int i = 0; i < 2; i++) {
#pragma unroll
        for (int rr = 0; rr < 2; rr++) {
            const int tl = wm * 32 + i * 16 + g + rr * 8;
            const int t  = t0 + tl;
#pragma unroll
            for (int j = 0; j < 5; j++) {
                const int ql = qc * 160 + wn * 40 + j * 8 + 2 * t4;
                const int q  = t0 + ql;
                float v0 = acc[i][j][2 * rr];
                float v1 = acc[i][j][2 * rr + 1];
                int wd0 = q - t, wd1 = wd0 + 1;
                v0 = (wd0 >= 0 && wd0 < WIN && q < TDIM)
                     ? v0 * exp2f((float)wd0 * lg) : 0.f;
                v1 = (wd1 >= 0 && wd1 < WIN && (q + 1) < TDIM)
                     ? v1 * exp2f((float)wd1 * lg) : 0.f;
                ((uint32_t*)Phb)[((size_t)tl * KQ + ql) >> 1] = pack_h2(v0, v1);
            }
        }
    }
}

// ---------------------------------------------------------------------------
// av_mma: out[t][c] = sum_{h,q} P * V, single-term fp16, Kstage=64,
// with FUSED GroupNorm epilogue (CTA covers 2 full groups x 64 rows).
// ---------------------------------------------------------------------------
#define AVSTAGE 27648
#define SMEM_AV (3 * AVSTAGE)

__global__ __launch_bounds__(256, 2) void av_mma(
    float* __restrict__ out,
    const float* __restrict__ wgt,
    const float* __restrict__ bias)
{
    extern __shared__ char smem[];
    const uint32_t sb = smem_u32(smem);
    const int tid = threadIdx.x;
    const int wid = tid >> 5;
    const int lane = tid & 31;
    const int wm = wid & 1, wn = wid >> 1;
    const int g = lane >> 2, t4 = lane & 3;

    const int cc   = blockIdx.x;      // 0..7
    const int tile = blockIdx.y;
    const int t0   = tile * TT;
    const int c0   = cc * 128;

    float acc[2][4][4];
#pragma unroll
    for (int i = 0; i < 2; i++)
#pragma unroll
        for (int j = 0; j < 4; j++)
#pragma unroll
            for (int q = 0; q < 4; q++) acc[i][j][q] = 0.f;

    auto load_stage = [&](int s, uint32_t stb) {
        const int kk0 = s * 64;
        const int h   = kk0 / KQ;
        const int ql  = kk0 - h * KQ;
#pragma unroll
        for (int i = 0; i < 6; i++) {
            const int c = tid + i * 256;
            if (c < 512) {
                const int row = c >> 3, ch = c & 7;
                const __half* src = g_Ph
                    + ((size_t)h * NTIL + tile) * TT * KQ
                    + (size_t)row * KQ + ql + ch * 8;
                CP16(stb + row * 144 + ch * 16, src);
            } else {
                const int rem = c - 512;
                const int row = rem >> 3, ch = rem & 7;
                int tg = t0 + ql + ch * 8;
                int sz = (tg < TDIM) ? 16 : 0;
                if (tg >= TDIM) tg = 0;
                const __half* src = g_Vth
                    + ((size_t)h * CDIM + c0 + row) * TDIM + tg;
                CP16Z(stb + 9216 + row * 144 + ch * 16, src, sz);
            }
        }
    };

    load_stage(0, sb);
    CP_COMMIT();
    load_stage(1, sb + AVSTAGE);
    CP_COMMIT();

#pragma unroll 1
    for (int s = 0; s < 40; s++) {
        if (s < 39) { CP_WAIT1(); } else { CP_WAIT0(); }
        __syncthreads();
        if (s + 2 < 40) {
            load_stage(s + 2, sb + ((s + 2) % 3) * AVSTAGE);
            CP_COMMIT();
        }
        const char* st = smem + (s % 3) * AVSTAGE;
        const char* Ah = st;
        const char* Bh = st + 9216;

#pragma unroll
        for (int kk = 0; kk < 64; kk += 16) {
            uint32_t ah[2][4];
#pragma unroll
            for (int i = 0; i < 2; i++) {
                const int b0 = (wm * 32 + i * 16 + g) * 144 + kk * 2 + t4 * 4;
                ah[i][0] = *(const uint32_t*)(Ah + b0);
                ah[i][1] = *(const uint32_t*)(Ah + b0 + 1152);
                ah[i][2] = *(const uint32_t*)(Ah + b0 + 16);
                ah[i][3] = *(const uint32_t*)(Ah + b0 + 1168);
            }
            uint32_t bh[4][2];
#pragma unroll
            for (int j = 0; j < 4; j++) {
                const int bb = (wn * 32 + j * 8 + g) * 144 + kk * 2 + t4 * 4;
                bh[j][0] = *(const uint32_t*)(Bh + bb);
                bh[j][1] = *(const uint32_t*)(Bh + bb + 16);
            }
#pragma unroll
            for (int i = 0; i < 2; i++)
#pragma unroll
                for (int j = 0; j < 4; j++)
                    mma_f16(acc[i][j], ah[i], bh[j]);
        }
    }

    // ---- fused GroupNorm epilogue ----
    // stage acc in smem: sf[64 t][132 c-stride] floats, then 2 groups/CTA.
    __syncthreads();
    float* sf = (float*)smem;                       // 64*132*4 = 33792 B
    float* smean = (float*)(smem + 33792);          // 128 floats
    float* srs   = smean + 128;                     // 128 floats
#pragma unroll
    for (int i = 0; i < 2; i++) {
#pragma unroll
        for (int rr = 0; rr < 2; rr++) {
            const int lt = wm * 32 + i * 16 + g + rr * 8;
#pragma unroll
            for (int j = 0; j < 4; j++) {
                const int lc = wn * 32 + j * 8 + 2 * t4;
                sf[lt * 132 + lc]     = acc[i][j][2 * rr];
                sf[lt * 132 + lc + 1] = acc[i][j][2 * rr + 1];
            }
        }
    }
    __syncthreads();
    if (tid < 128) {
        const int lt  = tid >> 1;
        const int grp = tid & 1;
        const float* row = sf + lt * 132 + grp * 64;
        float s = 0.f, sq = 0.f;
#pragma unroll
        for (int k = 0; k < 64; k++) {
            float v = row[k];
            s += v; sq += v * v;
        }
        float mean = s * (1.f / 64.f);
        float var  = sq * (1.f / 64.f) - mean * mean;
        smean[tid] = mean;
        srs[tid]   = rsqrtf(var + 1e-5f);
    }
    __syncthreads();
    {
        const int lt = tid >> 2;            // 0..63
        const int ck = (tid & 3) * 32;      // 0,32,64,96
        const int grp = ck >> 6;            // 0 or 1
        const float mean = smean[lt * 2 + grp];
        const float rs   = srs[lt * 2 + grp];
        float* o = out + (size_t)(t0 + lt) * CDIM + c0 + ck;
        const float* row = sf + lt * 132 + ck;
#pragma unroll
        for (int k = 0; k < 32; k += 4) {
            float4 w4 = *(const float4*)(wgt + c0 + ck + k);
            float4 b4 = *(const float4*)(bias + c0 + ck + k);
            float4 v  = make_float4(row[k], row[k + 1], row[k + 2], row[k + 3]);
            v.x = (v.x - mean) * rs * w4.x + b4.x;
            v.y = (v.y - mean) * rs * w4.y + b4.y;
            v.z = (v.z - mean) * rs * w4.z + b4.z;
            v.w = (v.w - mean) * rs * w4.w + b4.w;
            *(float4*)(o + k) = v;
        }
    }
}

// ---------------------------------------------------------------------------
extern "C" void kernel_launch(void* const* d_in, const int* in_sizes, int n_in,
                              void* d_out, int out_size)
{
    const float* X  = (const float*)d_in[0];
    const float* Wq = (const float*)d_in[1];
    const float* Wk = (const float*)d_in[2];
    const float* Wv = (const float*)d_in[3];
    const float* gw = (const float*)d_in[4];
    const float* gb = (const float*)d_in[5];
    float* out = (float*)d_out;

    prep_x<<<(TDIM * CDIM / 4) / 256, 256>>>(X);
    prep_w<<<dim3(NW / 32, CDIM / 32, 3), dim3(32, 8)>>>(Wq, Wk, Wv);

    cudaFuncSetAttribute(proj_mma, cudaFuncAttributeMaxDynamicSharedMemorySize,
                         SMEM_PROJ);
    proj_mma<<<dim3(16, 64, 3), 256, SMEM_PROJ>>>();

    transpose_v<<<dim3(CDIM / 64, TDIM / 64, HN), 256>>>();

    cudaFuncSetAttribute(qk_mma, cudaFuncAttributeMaxDynamicSharedMemorySize,
                         SMEM_QK);
    qk_mma<<<dim3(2, NTIL, HN), 256, SMEM_QK>>>();

    cudaFuncSetAttribute(av_mma, cudaFuncAttributeMaxDynamicSharedMemorySize,
                         SMEM_AV);
    av_mma<<<dim3(8, NTIL), 256, SMEM_AV>>>(out, gw, gb);
}

// round 16
// speedup vs baseline: 1.0035x; 1.0035x over previous
#include <cuda_runtime.h>
#include <cuda_fp16.h>
#include <math.h>
#include <stdint.h>

#define TDIM 2048
#define CDIM 1024
#define HN   8
#define NW   8192
#define WIN  256
#define KQ   320
#define TT   64
#define NTIL 32
#define GAMMA 0.96875f

// fp16 operands, all single precision.
__device__ __half g_Xh[(size_t)TDIM * CDIM];
__device__ __half g_Wth[(size_t)3 * NW * CDIM];            // [z][n][k]
__device__ __half g_Qh[(size_t)HN * TDIM * CDIM];
__device__ __half g_Kh[(size_t)HN * TDIM * CDIM];
__device__ __half g_Vh[(size_t)HN * TDIM * CDIM];          // [h][t][c]
__device__ __half g_Vth[(size_t)HN * CDIM * TDIM];         // [h][c][t]
__device__ __half g_Ph[(size_t)HN * NTIL * TT * KQ];       // [h][tile][t][q]

// ---------------------------------------------------------------------------
#define CP16(dst, src) \
    asm volatile("cp.async.cg.shared.global [%0], [%1], 16;" :: "r"(dst), "l"(src))
#define CP16Z(dst, src, sz) \
    asm volatile("cp.async.cg.shared.global [%0], [%1], 16, %2;" :: "r"(dst), "l"(src), "r"(sz))
#define CP_COMMIT() asm volatile("cp.async.commit_group;" ::: "memory")
#define CP_WAIT1()  asm volatile("cp.async.wait_group 1;" ::: "memory")
#define CP_WAIT0()  asm volatile("cp.async.wait_group 0;" ::: "memory")

__device__ __forceinline__ uint32_t smem_u32(const void* p) {
    uint32_t a;
    asm("{ .reg .u64 t; cvta.to.shared.u64 t, %1; cvt.u32.u64 %0, t; }"
        : "=r"(a) : "l"(p));
    return a;
}

__device__ __forceinline__ void mma_f16(float c[4], const uint32_t a[4],
                                        const uint32_t b[2]) {
    asm volatile(
        "mma.sync.aligned.m16n8k16.row.col.f32.f16.f16.f32 "
        "{%0,%1,%2,%3}, {%4,%5,%6,%7}, {%8,%9}, {%0,%1,%2,%3};"
        : "+f"(c[0]), "+f"(c[1]), "+f"(c[2]), "+f"(c[3])
        : "r"(a[0]), "r"(a[1]), "r"(a[2]), "r"(a[3]), "r"(b[0]), "r"(b[1]));
}

__device__ __forceinline__ uint32_t pack_h2(float v0, float v1) {
    __half2 h = __floats2half2_rn(v0, v1);
    return *(uint32_t*)&h;
}

// ---------------------------------------------------------------------------
// Prep: X -> fp16
// ---------------------------------------------------------------------------
__global__ __launch_bounds__(256) void prep_x(const float* __restrict__ X)
{
    int i = blockIdx.x * 256 + threadIdx.x;
    float4 v = ((const float4*)X)[i];
    ((uint2*)g_Xh)[i] = make_uint2(pack_h2(v.x, v.y), pack_h2(v.z, v.w));
}

// ---------------------------------------------------------------------------
// Prep: transpose W [K,N] -> Wt [N,K], fp16
// ---------------------------------------------------------------------------
__global__ __launch_bounds__(256) void prep_w(
    const float* __restrict__ Wq, const float* __restrict__ Wk,
    const float* __restrict__ Wv)
{
    const int z = blockIdx.z;
    const float* W = (z == 0) ? Wq : ((z == 1) ? Wk : Wv);
    const int n0 = blockIdx.x * 32;
    const int k0 = blockIdx.y * 32;

    __shared__ float t[32][33];
    const int tx = threadIdx.x, ty = threadIdx.y;
#pragma unroll
    for (int j = 0; j < 4; j++)
        t[ty + 8 * j][tx] = W[(size_t)(k0 + ty + 8 * j) * NW + n0 + tx];
    __syncthreads();
#pragma unroll
    for (int j = 0; j < 4; j++) {
        float v = t[tx][ty + 8 * j];
        size_t o = ((size_t)z * NW + n0 + ty + 8 * j) * CDIM + k0 + tx;
        g_Wth[o] = __float2half_rn(v);
    }
}

// ---------------------------------------------------------------------------
// Projection: single-term fp16, fused RoPE+SiLU, outputs Q/K/V fp16.
// (occ-2 is load-bearing.)
// ---------------------------------------------------------------------------
#define PSTAGE 20480
#define SMEM_PROJ (3 * PSTAGE)

__device__ __forceinline__ void proj_load_stage(
    uint32_t stb, int tid, int m0, int zn0, int k0)
{
#pragma unroll
    for (int i = 0; i < 4; i++) {
        const int c = tid + i * 256;
        if (c < 512) {
            const int row = c >> 2;
            const int ch  = c & 3;
            const __half* src = g_Xh + (size_t)(m0 + row) * CDIM + k0 + ch * 8;
            CP16(stb + row * 80 + ch * 16, src);
        } else {
            const int rem = c - 512;
            const int row = rem >> 2;
            const int ch  = rem & 3;
            const __half* src = g_Wth + (size_t)(zn0 + row) * CDIM + k0 + ch * 8;
            CP16(stb + 10240 + row * 80 + ch * 16, src);
        }
    }
}

__global__ __launch_bounds__(256, 2) void proj_mma()
{
    extern __shared__ char smem[];
    const uint32_t sb = smem_u32(smem);
    const int tid = threadIdx.x;
    const int wid = tid >> 5;
    const int lane = tid & 31;
    const int wm = wid & 1, wn = wid >> 1;
    const int g = lane >> 2, t4 = lane & 3;

    const int m0 = blockIdx.x * 128;
    const int n0 = blockIdx.y * 128;
    const int z  = blockIdx.z;
    const int zn0 = z * NW + n0;

    float acc[4][4][4];
#pragma unroll
    for (int i = 0; i < 4; i++)
#pragma unroll
        for (int j = 0; j < 4; j++)
#pragma unroll
            for (int q = 0; q < 4; q++) acc[i][j][q] = 0.f;

    proj_load_stage(sb, tid, m0, zn0, 0);
    CP_COMMIT();
    proj_load_stage(sb + PSTAGE, tid, m0, zn0, 32);
    CP_COMMIT();

#pragma unroll 1
    for (int s = 0; s < 32; s++) {
        if (s < 31) { CP_WAIT1(); } else { CP_WAIT0(); }
        __syncthreads();
        if (s + 2 < 32) {
            proj_load_stage(sb + ((s + 2) % 3) * PSTAGE, tid, m0, zn0, (s + 2) * 32);
            CP_COMMIT();
        }
        const char* st = smem + (s % 3) * PSTAGE;
        const char* Ah = st;
        const char* Bh = st + 10240;

#pragma unroll
        for (int kk = 0; kk < 32; kk += 16) {
            uint32_t ah[4][4];
#pragma unroll
            for (int i = 0; i < 4; i++) {
                const int b0 = (wm * 64 + i * 16 + g) * 80 + kk * 2 + t4 * 4;
                ah[i][0] = *(const uint32_t*)(Ah + b0);
                ah[i][1] = *(const uint32_t*)(Ah + b0 + 640);
                ah[i][2] = *(const uint32_t*)(Ah + b0 + 16);
                ah[i][3] = *(const uint32_t*)(Ah + b0 + 656);
            }
            uint32_t bh[4][2];
#pragma unroll
            for (int j = 0; j < 4; j++) {
                const int bb = (wn * 32 + j * 8 + g) * 80 + kk * 2 + t4 * 4;
                bh[j][0] = *(const uint32_t*)(Bh + bb);
                bh[j][1] = *(const uint32_t*)(Bh + bb + 16);
            }
#pragma unroll
            for (int i = 0; i < 4; i++)
#pragma unroll
                for (int j = 0; j < 4; j++)
                    mma_f16(acc[i][j], ah[i], bh[j]);
        }
    }

    // epilogue: RoPE (Q,K cols<64) + SiLU, fp16 store
    const int h  = n0 >> 10;
    const int cbase = (n0 & 1023) + wn * 32 + 2 * t4;
    const bool rope_blk = (z < 2) && ((n0 & 1023) == 0) && (wn < 2);

    __half* Hi = (z == 0) ? g_Qh : ((z == 1) ? g_Kh : g_Vh);
    Hi += (size_t)h * TDIM * CDIM;

#pragma unroll
    for (int i = 0; i < 4; i++) {
#pragma unroll
        for (int rr = 0; rr < 2; rr++) {
            const int r = m0 + wm * 64 + i * 16 + g + rr * 8;
#pragma unroll
            for (int j = 0; j < 4; j++) {
                const int col = cbase + j * 8;
                float v0 = acc[i][j][2 * rr];
                float v1 = acc[i][j][2 * rr + 1];
                if (rope_blk) {
                    int c2 = col >> 1;
                    float invf = (float)exp(-((double)(2 * c2) / 64.0) * log(10000.0));
                    float ang = (float)r * invf;
                    float sn, cs;
                    sincosf(ang, &sn, &cs);
                    float y0 = v0 * cs - v1 * sn;
                    float y1 = v1 * cs + v0 * sn;
                    v0 = y0; v1 = y1;
                }
                v0 = v0 / (1.f + expf(-v0));
                v1 = v1 / (1.f + expf(-v1));
                ((uint32_t*)Hi)[((size_t)r * CDIM + col) >> 1] = pack_h2(v0, v1);
            }
        }
    }
}

// ---------------------------------------------------------------------------
// qk_tv: FUSED kernel.  Blocks [0,512): qk scores (tensor-bound).
// Blocks [512,4608): V transpose (memory-bound) — overlaps with qk waves.
// qk: M=64(t) N=160(q), Kstage=64, stage: A@0(9216) B@9216(23040); 32256.
// ---------------------------------------------------------------------------
#define QKSTAGE 32256
#define SMEM_QK (3 * QKSTAGE)
#define QK_BLOCKS 512

__global__ __launch_bounds__(256, 2) void qk_tv()
{
    extern __shared__ char smem[];
    const int bi = blockIdx.x;
    const int tid = threadIdx.x;

    if (bi >= QK_BLOCKS) {
        // ---- V transpose path: [h][t][c] -> [h][c][t], 64x64 tiles ----
        const int tb = bi - QK_BLOCKS;
        const int c0 = (tb & 15) * 64;
        const int t0 = ((tb >> 4) & 31) * 64;
        const int h  = tb >> 9;

        unsigned short (*sm)[72] = (unsigned short(*)[72])smem;
        const unsigned short* Vh =
            (const unsigned short*)g_Vh + (size_t)h * TDIM * CDIM;
        {
            const int tl = tid >> 2;
            const int ck = (tid & 3) * 16;
            uint4 v0 = *(const uint4*)(Vh + (size_t)(t0 + tl) * CDIM + c0 + ck);
            uint4 v1 = *(const uint4*)(Vh + (size_t)(t0 + tl) * CDIM + c0 + ck + 8);
            const unsigned short* p0 = (const unsigned short*)&v0;
            const unsigned short* p1 = (const unsigned short*)&v1;
#pragma unroll
            for (int k = 0; k < 8; k++) {
                sm[ck + k][tl]     = p0[k];
                sm[ck + 8 + k][tl] = p1[k];
            }
        }
        __syncthreads();
        {
            const int cl = tid >> 2;
            const int tk = (tid & 3) * 16;
            unsigned short* dst = (unsigned short*)g_Vth
                + ((size_t)h * CDIM + c0 + cl) * TDIM + t0 + tk;
            *(uint4*)(dst)     = *(const uint4*)(&sm[cl][tk]);
            *(uint4*)(dst + 8) = *(const uint4*)(&sm[cl][tk + 8]);
        }
        return;
    }

    // ---- qk path ----
    const uint32_t sb = smem_u32(smem);
    const int wid = tid >> 5;
    const int lane = tid & 31;
    const int wm = wid & 1, wn = wid >> 1;
    const int g = lane >> 2, t4 = lane & 3;

    const int qc   = bi & 1;
    const int tile = (bi >> 1) & 31;
    const int h    = bi >> 6;
    const int t0   = tile * TT;
    const int q0   = t0 + qc * 160;

    const __half* Kh = g_Kh + (size_t)h * TDIM * CDIM;
    const __half* Qh = g_Qh + (size_t)h * TDIM * CDIM;

    float acc[2][5][4];
#pragma unroll
    for (int i = 0; i < 2; i++)
#pragma unroll
        for (int j = 0; j < 5; j++)
#pragma unroll
            for (int q = 0; q < 4; q++) acc[i][j][q] = 0.f;

    auto load_stage = [&](int s, uint32_t stb) {
        const int k0 = s * 64;
#pragma unroll
        for (int i = 0; i < 7; i++) {
            const int c = tid + i * 256;
            if (c < 512) {
                const int row = c >> 3, ch = c & 7;
                const __half* src = Kh + (size_t)(t0 + row) * CDIM + k0 + ch * 8;
                CP16(stb + row * 144 + ch * 16, src);
            } else {
                const int rem = c - 512;
                const int row = rem >> 3, ch = rem & 7;
                int q = q0 + row;
                int sz = (q < TDIM) ? 16 : 0;
                if (q >= TDIM) q = 0;
                const __half* src = Qh + (size_t)q * CDIM + k0 + ch * 8;
                CP16Z(stb + 9216 + row * 144 + ch * 16, src, sz);
            }
        }
    };

    load_stage(0, sb);
    CP_COMMIT();
    load_stage(1, sb + QKSTAGE);
    CP_COMMIT();

#pragma unroll 1
    for (int s = 0; s < 16; s++) {
        if (s < 15) { CP_WAIT1(); } else { CP_WAIT0(); }
        __syncthreads();
        if (s + 2 < 16) {
            load_stage(s + 2, sb + ((s + 2) % 3) * QKSTAGE);
            CP_COMMIT();
        }
        const char* st = smem + (s % 3) * QKSTAGE;
        const char* Ah = st;
        const char* Bh = st + 9216;

#pragma unroll
        for (int kk = 0; kk < 64; kk += 16) {
            uint32_t ah[2][4];
#pragma unroll
            for (int i = 0; i < 2; i++) {
                const int b0 = (wm * 32 + i * 16 + g) * 144 + kk * 2 + t4 * 4;
                ah[i][0] = *(const uint32_t*)(Ah + b0);
                ah[i][1] = *(const uint32_t*)(Ah + b0 + 1152);
                ah[i][2] = *(const uint32_t*)(Ah + b0 + 16);
                ah[i][3] = *(const uint32_t*)(Ah + b0 + 1168);
            }
            uint32_t bh[5][2];
#pragma unroll
            for (int j = 0; j < 5; j++) {
                const int bb = (wn * 40 + j * 8 + g) * 144 + kk * 2 + t4 * 4;
                bh[j][0] = *(const uint32_t*)(Bh + bb);
                bh[j][1] = *(const uint32_t*)(Bh + bb + 16);
            }
#pragma unroll
            for (int i = 0; i < 2; i++)
#pragma unroll
                for (int j = 0; j < 5; j++)
                    mma_f16(acc[i][j], ah[i], bh[j]);
        }
    }

    // epilogue: decay + mask, fp16 store P
    const float lg = log2f(GAMMA);
    __half* Phb = g_Ph + ((size_t)h * NTIL + tile) * TT * KQ;
#pragma unroll
    for (int i = 0; i < 2; i++) {
#pragma unroll
        for (int rr = 0; rr < 2; rr++) {
            const int tl = wm * 32 + i * 16 + g + rr * 8;
            const int t  = t0 + tl;
#pragma unroll
            for (int j = 0; j < 5; j++) {
                const int ql = qc * 160 + wn * 40 + j * 8 + 2 * t4;
                const int q  = t0 + ql;
                float v0 = acc[i][j][2 * rr];
                float v1 = acc[i][j][2 * rr + 1];
                int wd0 = q - t, wd1 = wd0 + 1;
                v0 = (wd0 >= 0 && wd0 < WIN && q < TDIM)
                     ? v0 * exp2f((float)wd0 * lg) : 0.f;
                v1 = (wd1 >= 0 && wd1 < WIN && (q + 1) < TDIM)
                     ? v1 * exp2f((float)wd1 * lg) : 0.f;
                ((uint32_t*)Phb)[((size_t)tl * KQ + ql) >> 1] = pack_h2(v0, v1);
            }
        }
    }
}

// ---------------------------------------------------------------------------
// av_mma: out[t][c] = sum_{h,q} P * V, single-term fp16, Kstage=64,
// with FUSED GroupNorm epilogue (CTA covers 2 full groups x 64 rows).
// ---------------------------------------------------------------------------
#define AVSTAGE 27648
#define SMEM_AV (3 * AVSTAGE)

__global__ __launch_bounds__(256, 2) void av_mma(
    float* __restrict__ out,
    const float* __restrict__ wgt,
    const float* __restrict__ bias)
{
    extern __shared__ char smem[];
    const uint32_t sb = smem_u32(smem);
    const int tid = threadIdx.x;
    const int wid = tid >> 5;
    const int lane = tid & 31;
    const int wm = wid & 1, wn = wid >> 1;
    const int g = lane >> 2, t4 = lane & 3;

    const int cc   = blockIdx.x;      // 0..7
    const int tile = blockIdx.y;
    const int t0   = tile * TT;
    const int c0   = cc * 128;

    float acc[2][4][4];
#pragma unroll
    for (int i = 0; i < 2; i++)
#pragma unroll
        for (int j = 0; j < 4; j++)
#pragma unroll
            for (int q = 0; q < 4; q++) acc[i][j][q] = 0.f;

    auto load_stage = [&](int s, uint32_t stb) {
        const int kk0 = s * 64;
        const int h   = kk0 / KQ;
        const int ql  = kk0 - h * KQ;
#pragma unroll
        for (int i = 0; i < 6; i++) {
            const int c = tid + i * 256;
            if (c < 512) {
                const int row = c >> 3, ch = c & 7;
                const __half* src = g_Ph
                    + ((size_t)h * NTIL + tile) * TT * KQ
                    + (size_t)row * KQ + ql + ch * 8;
                CP16(stb + row * 144 + ch * 16, src);
            } else {
                const int rem = c - 512;
                const int row = rem >> 3, ch = rem & 7;
                int tg = t0 + ql + ch * 8;
                int sz = (tg < TDIM) ? 16 : 0;
                if (tg >= TDIM) tg = 0;
                const __half* src = g_Vth
                    + ((size_t)h * CDIM + c0 + row) * TDIM + tg;
                CP16Z(stb + 9216 + row * 144 + ch * 16, src, sz);
            }
        }
    };

    load_stage(0, sb);
    CP_COMMIT();
    load_stage(1, sb + AVSTAGE);
    CP_COMMIT();

#pragma unroll 1
    for (int s = 0; s < 40; s++) {
        if (s < 39) { CP_WAIT1(); } else { CP_WAIT0(); }
        __syncthreads();
        if (s + 2 < 40) {
            load_stage(s + 2, sb + ((s + 2) % 3) * AVSTAGE);
            CP_COMMIT();
        }
        const char* st = smem + (s % 3) * AVSTAGE;
        const char* Ah = st;
        const char* Bh = st + 9216;

#pragma unroll
        for (int kk = 0; kk < 64; kk += 16) {
            uint32_t ah[2][4];
#pragma unroll
            for (int i = 0; i < 2; i++) {
                const int b0 = (wm * 32 + i * 16 + g) * 144 + kk * 2 + t4 * 4;
                ah[i][0] = *(const uint32_t*)(Ah + b0);
                ah[i][1] = *(const uint32_t*)(Ah + b0 + 1152);
                ah[i][2] = *(const uint32_t*)(Ah + b0 + 16);
                ah[i][3] = *(const uint32_t*)(Ah + b0 + 1168);
            }
            uint32_t bh[4][2];
#pragma unroll
            for (int j = 0; j < 4; j++) {
                const int bb = (wn * 32 + j * 8 + g) * 144 + kk * 2 + t4 * 4;
                bh[j][0] = *(const uint32_t*)(Bh + bb);
                bh[j][1] = *(const uint32_t*)(Bh + bb + 16);
            }
#pragma unroll
            for (int i = 0; i < 2; i++)
#pragma unroll
                for (int j = 0; j < 4; j++)
                    mma_f16(acc[i][j], ah[i], bh[j]);
        }
    }

    // ---- fused GroupNorm epilogue ----
    __syncthreads();
    float* sf = (float*)smem;                       // 64*132*4 = 33792 B
    float* smean = (float*)(smem + 33792);          // 128 floats
    float* srs   = smean + 128;                     // 128 floats
#pragma unroll
    for (int i = 0; i < 2; i++) {
#pragma unroll
        for (int rr = 0; rr < 2; rr++) {
            const int lt = wm * 32 + i * 16 + g + rr * 8;
#pragma unroll
            for (int j = 0; j < 4; j++) {
                const int lc = wn * 32 + j * 8 + 2 * t4;
                sf[lt * 132 + lc]     = acc[i][j][2 * rr];
                sf[lt * 132 + lc + 1] = acc[i][j][2 * rr + 1];
            }
        }
    }
    __syncthreads();
    if (tid < 128) {
        const int lt  = tid >> 1;
        const int grp = tid & 1;
        const float* row = sf + lt * 132 + grp * 64;
        float s = 0.f, sq = 0.f;
#pragma unroll
        for (int k = 0; k < 64; k++) {
            float v = row[k];
            s += v; sq += v * v;
        }
        float mean = s * (1.f / 64.f);
        float var  = sq * (1.f / 64.f) - mean * mean;
        smean[tid] = mean;
        srs[tid]   = rsqrtf(var + 1e-5f);
    }
    __syncthreads();
    {
        const int lt = tid >> 2;
        const int ck = (tid & 3) * 32;
        const int grp = ck >> 6;
        const float mean = smean[lt * 2 + grp];
        const float rs   = srs[lt * 2 + grp];
        float* o = out + (size_t)(t0 + lt) * CDIM + c0 + ck;
        const float* row = sf + lt * 132 + ck;
#pragma unroll
        for (int k = 0; k < 32; k += 4) {
            float4 w4 = *(const float4*)(wgt + c0 + ck + k);
            float4 b4 = *(const float4*)(bias + c0 + ck + k);
            float4 v  = make_float4(row[k], row[k + 1], row[k + 2], row[k + 3]);
            v.x = (v.x - mean) * rs * w4.x + b4.x;
            v.y = (v.y - mean) * rs * w4.y + b4.y;
            v.z = (v.z - mean) * rs * w4.z + b4.z;
            v.w = (v.w - mean) * rs * w4.w + b4.w;
            *(float4*)(o + k) = v;
        }
    }
}

// ---------------------------------------------------------------------------
extern "C" void kernel_launch(void* const* d_in, const int* in_sizes, int n_in,
                              void* d_out, int out_size)
{
    const float* X  = (const float*)d_in[0];
    const float* Wq = (const float*)d_in[1];
    const float* Wk = (const float*)d_in[2];
    const float* Wv = (const float*)d_in[3];
    const float* gw = (const float*)d_in[4];
    const float* gb = (const float*)d_in[5];
    float* out = (float*)d_out;

    prep_x<<<(TDIM * CDIM / 4) / 256, 256>>>(X);
    prep_w<<<dim3(NW / 32, CDIM / 32, 3), dim3(32, 8)>>>(Wq, Wk, Wv);

    cudaFuncSetAttribute(proj_mma, cudaFuncAttributeMaxDynamicSharedMemorySize,
                         SMEM_PROJ);
    proj_mma<<<dim3(16, 64, 3), 256, SMEM_PROJ>>>();

    cudaFuncSetAttribute(qk_tv, cudaFuncAttributeMaxDynamicSharedMemorySize,
                         SMEM_QK);
    qk_tv<<<QK_BLOCKS + (CDIM / 64) * (TDIM / 64) * HN, 256, SMEM_QK>>>();

    cudaFuncSetAttribute(av_mma, cudaFuncAttributeMaxDynamicSharedMemorySize,
                         SMEM_AV);
    av_mma<<<dim3(8, NTIL), 256, SMEM_AV>>>(out, gw, gb);
}

// round 17
// speedup vs baseline: 1.0078x; 1.0043x over previous
#include <cuda_runtime.h>
#include <cuda_fp16.h>
#include <math.h>
#include <stdint.h>

#define TDIM 2048
#define CDIM 1024
#define HN   8
#define NW   8192
#define WIN  256
#define KQ   320
#define TT   64
#define NTIL 32
#define GAMMA 0.96875f

// fp16 operands, all single precision.
__device__ __half g_Xh[(size_t)TDIM * CDIM];
__device__ __half g_Wth[(size_t)3 * NW * CDIM];            // [z][n][k]
__device__ __half g_Qh[(size_t)HN * TDIM * CDIM];
__device__ __half g_Kh[(size_t)HN * TDIM * CDIM];
__device__ __half g_Vh[(size_t)HN * TDIM * CDIM];          // [h][t][c]
__device__ __half g_Vth[(size_t)HN * CDIM * TDIM];         // [h][c][t]
__device__ __half g_Ph[(size_t)HN * NTIL * TT * KQ];       // [h][tile][t][q]

// ---------------------------------------------------------------------------
#define CP16(dst, src) \
    asm volatile("cp.async.cg.shared.global [%0], [%1], 16;" :: "r"(dst), "l"(src))
#define CP16Z(dst, src, sz) \
    asm volatile("cp.async.cg.shared.global [%0], [%1], 16, %2;" :: "r"(dst), "l"(src), "r"(sz))
#define CP_COMMIT() asm volatile("cp.async.commit_group;" ::: "memory")
#define CP_WAIT1()  asm volatile("cp.async.wait_group 1;" ::: "memory")
#define CP_WAIT0()  asm volatile("cp.async.wait_group 0;" ::: "memory")

__device__ __forceinline__ uint32_t smem_u32(const void* p) {
    uint32_t a;
    asm("{ .reg .u64 t; cvta.to.shared.u64 t, %1; cvt.u32.u64 %0, t; }"
        : "=r"(a) : "l"(p));
    return a;
}

__device__ __forceinline__ void mma_f16(float c[4], const uint32_t a[4],
                                        const uint32_t b[2]) {
    asm volatile(
        "mma.sync.aligned.m16n8k16.row.col.f32.f16.f16.f32 "
        "{%0,%1,%2,%3}, {%4,%5,%6,%7}, {%8,%9}, {%0,%1,%2,%3};"
        : "+f"(c[0]), "+f"(c[1]), "+f"(c[2]), "+f"(c[3])
        : "r"(a[0]), "r"(a[1]), "r"(a[2]), "r"(a[3]), "r"(b[0]), "r"(b[1]));
}

__device__ __forceinline__ uint32_t pack_h2(float v0, float v1) {
    __half2 h = __floats2half2_rn(v0, v1);
    return *(uint32_t*)&h;
}

// ---------------------------------------------------------------------------
// prep_all: fused prep.  Blocks [0, WB): transpose+convert W -> Wt fp16.
// Blocks [WB, WB+XB): convert X -> fp16.
// WB = (NW/32)*(CDIM/32)*3 = 24576,  XB = TDIM*CDIM/4/256 = 2048.
// ---------------------------------------------------------------------------
#define WB_BLOCKS 24576
#define XB_BLOCKS 2048

__global__ __launch_bounds__(256) void prep_all(
    const float* __restrict__ X,
    const float* __restrict__ Wq, const float* __restrict__ Wk,
    const float* __restrict__ Wv)
{
    const int bi = blockIdx.x;
    const int tid = threadIdx.x;

    if (bi >= WB_BLOCKS) {
        // ---- X path ----
        int i = (bi - WB_BLOCKS) * 256 + tid;
        float4 v = ((const float4*)X)[i];
        ((uint2*)g_Xh)[i] = make_uint2(pack_h2(v.x, v.y), pack_h2(v.z, v.w));
        return;
    }

    // ---- W path: transpose [K,N] -> [N,K] fp16, 32x32 tiles ----
    const int z  = bi / 8192;                 // 256*32 = 8192 blocks per z
    const int r  = bi - z * 8192;
    const int n0 = (r & 255) * 32;
    const int k0 = (r >> 8) * 32;
    const float* W = (z == 0) ? Wq : ((z == 1) ? Wk : Wv);

    __shared__ float t[32][33];
    const int tx = tid & 31, ty = tid >> 5;
#pragma unroll
    for (int j = 0; j < 4; j++)
        t[ty + 8 * j][tx] = W[(size_t)(k0 + ty + 8 * j) * NW + n0 + tx];
    __syncthreads();
#pragma unroll
    for (int j = 0; j < 4; j++) {
        float v = t[tx][ty + 8 * j];
        size_t o = ((size_t)z * NW + n0 + ty + 8 * j) * CDIM + k0 + tx;
        g_Wth[o] = __float2half_rn(v);
    }
}

// ---------------------------------------------------------------------------
// Projection: single-term fp16, fused RoPE+SiLU, outputs Q/K/V fp16.
// (occ-2 is load-bearing.)
// ---------------------------------------------------------------------------
#define PSTAGE 20480
#define SMEM_PROJ (3 * PSTAGE)

__device__ __forceinline__ void proj_load_stage(
    uint32_t stb, int tid, int m0, int zn0, int k0)
{
#pragma unroll
    for (int i = 0; i < 4; i++) {
        const int c = tid + i * 256;
        if (c < 512) {
            const int row = c >> 2;
            const int ch  = c & 3;
            const __half* src = g_Xh + (size_t)(m0 + row) * CDIM + k0 + ch * 8;
            CP16(stb + row * 80 + ch * 16, src);
        } else {
            const int rem = c - 512;
            const int row = rem >> 2;
            const int ch  = rem & 3;
            const __half* src = g_Wth + (size_t)(zn0 + row) * CDIM + k0 + ch * 8;
            CP16(stb + 10240 + row * 80 + ch * 16, src);
        }
    }
}

__global__ __launch_bounds__(256, 2) void proj_mma()
{
    extern __shared__ char smem[];
    const uint32_t sb = smem_u32(smem);
    const int tid = threadIdx.x;
    const int wid = tid >> 5;
    const int lane = tid & 31;
    const int wm = wid & 1, wn = wid >> 1;
    const int g = lane >> 2, t4 = lane & 3;

    const int m0 = blockIdx.x * 128;
    const int n0 = blockIdx.y * 128;
    const int z  = blockIdx.z;
    const int zn0 = z * NW + n0;

    float acc[4][4][4];
#pragma unroll
    for (int i = 0; i < 4; i++)
#pragma unroll
        for (int j = 0; j < 4; j++)
#pragma unroll
            for (int q = 0; q < 4; q++) acc[i][j][q] = 0.f;

    proj_load_stage(sb, tid, m0, zn0, 0);
    CP_COMMIT();
    proj_load_stage(sb + PSTAGE, tid, m0, zn0, 32);
    CP_COMMIT();

#pragma unroll 1
    for (int s = 0; s < 32; s++) {
        if (s < 31) { CP_WAIT1(); } else { CP_WAIT0(); }
        __syncthreads();
        if (s + 2 < 32) {
            proj_load_stage(sb + ((s + 2) % 3) * PSTAGE, tid, m0, zn0, (s + 2) * 32);
            CP_COMMIT();
        }
        const char* st = smem + (s % 3) * PSTAGE;
        const char* Ah = st;
        const char* Bh = st + 10240;

#pragma unroll
        for (int kk = 0; kk < 32; kk += 16) {
            uint32_t ah[4][4];
#pragma unroll
            for (int i = 0; i < 4; i++) {
                const int b0 = (wm * 64 + i * 16 + g) * 80 + kk * 2 + t4 * 4;
                ah[i][0] = *(const uint32_t*)(Ah + b0);
                ah[i][1] = *(const uint32_t*)(Ah + b0 + 640);
                ah[i][2] = *(const uint32_t*)(Ah + b0 + 16);
                ah[i][3] = *(const uint32_t*)(Ah + b0 + 656);
            }
            uint32_t bh[4][2];
#pragma unroll
            for (int j = 0; j < 4; j++) {
                const int bb = (wn * 32 + j * 8 + g) * 80 + kk * 2 + t4 * 4;
                bh[j][0] = *(const uint32_t*)(Bh + bb);
                bh[j][1] = *(const uint32_t*)(Bh + bb + 16);
            }
#pragma unroll
            for (int i = 0; i < 4; i++)
#pragma unroll
                for (int j = 0; j < 4; j++)
                    mma_f16(acc[i][j], ah[i], bh[j]);
        }
    }

    // epilogue: RoPE (Q,K cols<64) + SiLU, fp16 store
    const int h  = n0 >> 10;
    const int cbase = (n0 & 1023) + wn * 32 + 2 * t4;
    const bool rope_blk = (z < 2) && ((n0 & 1023) == 0) && (wn < 2);

    __half* Hi = (z == 0) ? g_Qh : ((z == 1) ? g_Kh : g_Vh);
    Hi += (size_t)h * TDIM * CDIM;

#pragma unroll
    for (int i = 0; i < 4; i++) {
#pragma unroll
        for (int rr = 0; rr < 2; rr++) {
            const int r = m0 + wm * 64 + i * 16 + g + rr * 8;
#pragma unroll
            for (int j = 0; j < 4; j++) {
                const int col = cbase + j * 8;
                float v0 = acc[i][j][2 * rr];
                float v1 = acc[i][j][2 * rr + 1];
                if (rope_blk) {
                    int c2 = col >> 1;
                    float invf = (float)exp(-((double)(2 * c2) / 64.0) * log(10000.0));
                    float ang = (float)r * invf;
                    float sn, cs;
                    sincosf(ang, &sn, &cs);
                    float y0 = v0 * cs - v1 * sn;
                    float y1 = v1 * cs + v0 * sn;
                    v0 = y0; v1 = y1;
                }
                v0 = v0 / (1.f + expf(-v0));
                v1 = v1 / (1.f + expf(-v1));
                ((uint32_t*)Hi)[((size_t)r * CDIM + col) >> 1] = pack_h2(v0, v1);
            }
        }
    }
}

// ---------------------------------------------------------------------------
// qk_tv: FUSED kernel.  Blocks [0,512): qk scores (tensor-bound).
// Blocks [512,4608): V transpose (memory-bound) — overlaps with qk waves.
// ---------------------------------------------------------------------------
#define QKSTAGE 32256
#define SMEM_QK (3 * QKSTAGE)
#define QK_BLOCKS 512

__global__ __launch_bounds__(256, 2) void qk_tv()
{
    extern __shared__ char smem[];
    const int bi = blockIdx.x;
    const int tid = threadIdx.x;

    if (bi >= QK_BLOCKS) {
        // ---- V transpose path: [h][t][c] -> [h][c][t], 64x64 tiles ----
        const int tb = bi - QK_BLOCKS;
        const int c0 = (tb & 15) * 64;
        const int t0 = ((tb >> 4) & 31) * 64;
        const int h  = tb >> 9;

        unsigned short (*sm)[72] = (unsigned short(*)[72])smem;
        const unsigned short* Vh =
            (const unsigned short*)g_Vh + (size_t)h * TDIM * CDIM;
        {
            const int tl = tid >> 2;
            const int ck = (tid & 3) * 16;
            uint4 v0 = *(const uint4*)(Vh + (size_t)(t0 + tl) * CDIM + c0 + ck);
            uint4 v1 = *(const uint4*)(Vh + (size_t)(t0 + tl) * CDIM + c0 + ck + 8);
            const unsigned short* p0 = (const unsigned short*)&v0;
            const unsigned short* p1 = (const unsigned short*)&v1;
#pragma unroll
            for (int k = 0; k < 8; k++) {
                sm[ck + k][tl]     = p0[k];
                sm[ck + 8 + k][tl] = p1[k];
            }
        }
        __syncthreads();
        {
            const int cl = tid >> 2;
            const int tk = (tid & 3) * 16;
            unsigned short* dst = (unsigned short*)g_Vth
                + ((size_t)h * CDIM + c0 + cl) * TDIM + t0 + tk;
            *(uint4*)(dst)     = *(const uint4*)(&sm[cl][tk]);
            *(uint4*)(dst + 8) = *(const uint4*)(&sm[cl][tk + 8]);
        }
        return;
    }

    // ---- qk path ----
    const uint32_t sb = smem_u32(smem);
    const int wid = tid >> 5;
    const int lane = tid & 31;
    const int wm = wid & 1, wn = wid >> 1;
    const int g = lane >> 2, t4 = lane & 3;

    const int qc   = bi & 1;
    const int tile = (bi >> 1) & 31;
    const int h    = bi >> 6;
    const int t0   = tile * TT;
    const int q0   = t0 + qc * 160;

    const __half* Kh = g_Kh + (size_t)h * TDIM * CDIM;
    const __half* Qh = g_Qh + (size_t)h * TDIM * CDIM;

    float acc[2][5][4];
#pragma unroll
    for (int i = 0; i < 2; i++)
#pragma unroll
        for (int j = 0; j < 5; j++)
#pragma unroll
            for (int q = 0; q < 4; q++) acc[i][j][q] = 0.f;

    auto load_stage = [&](int s, uint32_t stb) {
        const int k0 = s * 64;
#pragma unroll
        for (int i = 0; i < 7; i++) {
            const int c = tid + i * 256;
            if (c < 512) {
                const int row = c >> 3, ch = c & 7;
                const __half* src = Kh + (size_t)(t0 + row) * CDIM + k0 + ch * 8;
                CP16(stb + row * 144 + ch * 16, src);
            } else {
                const int rem = c - 512;
                const int row = rem >> 3, ch = rem & 7;
                int q = q0 + row;
                int sz = (q < TDIM) ? 16 : 0;
                if (q >= TDIM) q = 0;
                const __half* src = Qh + (size_t)q * CDIM + k0 + ch * 8;
                CP16Z(stb + 9216 + row * 144 + ch * 16, src, sz);
            }
        }
    };

    load_stage(0, sb);
    CP_COMMIT();
    load_stage(1, sb + QKSTAGE);
    CP_COMMIT();

#pragma unroll 1
    for (int s = 0; s < 16; s++) {
        if (s < 15) { CP_WAIT1(); } else { CP_WAIT0(); }
        __syncthreads();
        if (s + 2 < 16) {
            load_stage(s + 2, sb + ((s + 2) % 3) * QKSTAGE);
            CP_COMMIT();
        }
        const char* st = smem + (s % 3) * QKSTAGE;
        const char* Ah = st;
        const char* Bh = st + 9216;

#pragma unroll
        for (int kk = 0; kk < 64; kk += 16) {
            uint32_t ah[2][4];
#pragma unroll
            for (int i = 0; i < 2; i++) {
                const int b0 = (wm * 32 + i * 16 + g) * 144 + kk * 2 + t4 * 4;
                ah[i][0] = *(const uint32_t*)(Ah + b0);
                ah[i][1] = *(const uint32_t*)(Ah + b0 + 1152);
                ah[i][2] = *(const uint32_t*)(Ah + b0 + 16);
                ah[i][3] = *(const uint32_t*)(Ah + b0 + 1168);
            }
            uint32_t bh[5][2];
#pragma unroll
            for (int j = 0; j < 5; j++) {
                const int bb = (wn * 40 + j * 8 + g) * 144 + kk * 2 + t4 * 4;
                bh[j][0] = *(const uint32_t*)(Bh + bb);
                bh[j][1] = *(const uint32_t*)(Bh + bb + 16);
            }
#pragma unroll
            for (int i = 0; i < 2; i++)
#pragma unroll
                for (int j = 0; j < 5; j++)
                    mma_f16(acc[i][j], ah[i], bh[j]);
        }
    }

    // epilogue: decay + mask, fp16 store P
    const float lg = log2f(GAMMA);
    __half* Phb = g_Ph + ((size_t)h * NTIL + tile) * TT * KQ;
#pragma unroll
    for (int i = 0; i < 2; i++) {
#pragma unroll
        for (int rr = 0; rr < 2; rr++) {
            const int tl = wm * 32 + i * 16 + g + rr * 8;
            const int t  = t0 + tl;
#pragma unroll
            for (int j = 0; j < 5; j++) {
                const int ql = qc * 160 + wn * 40 + j * 8 + 2 * t4;
                const int q  = t0 + ql;
                float v0 = acc[i][j][2 * rr];
                float v1 = acc[i][j][2 * rr + 1];
                int wd0 = q - t, wd1 = wd0 + 1;
                v0 = (wd0 >= 0 && wd0 < WIN && q < TDIM)
                     ? v0 * exp2f((float)wd0 * lg) : 0.f;
                v1 = (wd1 >= 0 && wd1 < WIN && (q + 1) < TDIM)
                     ? v1 * exp2f((float)wd1 * lg) : 0.f;
                ((uint32_t*)Phb)[((size_t)tl * KQ + ql) >> 1] = pack_h2(v0, v1);
            }
        }
    }
}

// ---------------------------------------------------------------------------
// av_mma: out[t][c] = sum_{h,q} P * V, single-term fp16, Kstage=64,
// with FUSED GroupNorm epilogue (CTA covers 2 full groups x 64 rows).
// ---------------------------------------------------------------------------
#define AVSTAGE 27648
#define SMEM_AV (3 * AVSTAGE)

__global__ __launch_bounds__(256, 2) void av_mma(
    float* __restrict__ out,
    const float* __restrict__ wgt,
    const float* __restrict__ bias)
{
    extern __shared__ char smem[];
    const uint32_t sb = smem_u32(smem);
    const int tid = threadIdx.x;
    const int wid = tid >> 5;
    const int lane = tid & 31;
    const int wm = wid & 1, wn = wid >> 1;
    const int g = lane >> 2, t4 = lane & 3;

    const int cc   = blockIdx.x;      // 0..7
    const int tile = blockIdx.y;
    const int t0   = tile * TT;
    const int c0   = cc * 128;

    float acc[2][4][4];
#pragma unroll
    for (int i = 0; i < 2; i++)
#pragma unroll
        for (int j = 0; j < 4; j++)
#pragma unroll
            for (int q = 0; q < 4; q++) acc[i][j][q] = 0.f;

    auto load_stage = [&](int s, uint32_t stb) {
        const int kk0 = s * 64;
        const int h   = kk0 / KQ;
        const int ql  = kk0 - h * KQ;
#pragma unroll
        for (int i = 0; i < 6; i++) {
            const int c = tid + i * 256;
            if (c < 512) {
                const int row = c >> 3, ch = c & 7;
                const __half* src = g_Ph
                    + ((size_t)h * NTIL + tile) * TT * KQ
                    + (size_t)row * KQ + ql + ch * 8;
                CP16(stb + row * 144 + ch * 16, src);
            } else {
                const int rem = c - 512;
                const int row = rem >> 3, ch = rem & 7;
                int tg = t0 + ql + ch * 8;
                int sz = (tg < TDIM) ? 16 : 0;
                if (tg >= TDIM) tg = 0;
                const __half* src = g_Vth
                    + ((size_t)h * CDIM + c0 + row) * TDIM + tg;
                CP16Z(stb + 9216 + row * 144 + ch * 16, src, sz);
            }
        }
    };

    load_stage(0, sb);
    CP_COMMIT();
    load_stage(1, sb + AVSTAGE);
    CP_COMMIT();

#pragma unroll 1
    for (int s = 0; s < 40; s++) {
        if (s < 39) { CP_WAIT1(); } else { CP_WAIT0(); }
        __syncthreads();
        if (s + 2 < 40) {
            load_stage(s + 2, sb + ((s + 2) % 3) * AVSTAGE);
            CP_COMMIT();
        }
        const char* st = smem + (s % 3) * AVSTAGE;
        const char* Ah = st;
        const char* Bh = st + 9216;

#pragma unroll
        for (int kk = 0; kk < 64; kk += 16) {
            uint32_t ah[2][4];
#pragma unroll
            for (int i = 0; i < 2; i++) {
                const int b0 = (wm * 32 + i * 16 + g) * 144 + kk * 2 + t4 * 4;
                ah[i][0] = *(const uint32_t*)(Ah + b0);
                ah[i][1] = *(const uint32_t*)(Ah + b0 + 1152);
                ah[i][2] = *(const uint32_t*)(Ah + b0 + 16);
                ah[i][3] = *(const uint32_t*)(Ah + b0 + 1168);
            }
            uint32_t bh[4][2];
#pragma unroll
            for (int j = 0; j < 4; j++) {
                const int bb = (wn * 32 + j * 8 + g) * 144 + kk * 2 + t4 * 4;
                bh[j][0] = *(const uint32_t*)(Bh + bb);
                bh[j][1] = *(const uint32_t*)(Bh + bb + 16);
            }
#pragma unroll
            for (int i = 0; i < 2; i++)
#pragma unroll
                for (int j = 0; j < 4; j++)
                    mma_f16(acc[i][j], ah[i], bh[j]);
        }
    }

    // ---- fused GroupNorm epilogue ----
    __syncthreads();
    float* sf = (float*)smem;                       // 64*132*4 = 33792 B
    float* smean = (float*)(smem + 33792);          // 128 floats
    float* srs   = smean + 128;                     // 128 floats
#pragma unroll
    for (int i = 0; i < 2; i++) {
#pragma unroll
        for (int rr = 0; rr < 2; rr++) {
            const int lt = wm * 32 + i * 16 + g + rr * 8;
#pragma unroll
            for (int j = 0; j < 4; j++) {
                const int lc = wn * 32 + j * 8 + 2 * t4;
                sf[lt * 132 + lc]     = acc[i][j][2 * rr];
                sf[lt * 132 + lc + 1] = acc[i][j][2 * rr + 1];
            }
        }
    }
    __syncthreads();
    if (tid < 128) {
        const int lt  = tid >> 1;
        const int grp = tid & 1;
        const float* row = sf + lt * 132 + grp * 64;
        float s = 0.f, sq = 0.f;
#pragma unroll
        for (int k = 0; k < 64; k++) {
            float v = row[k];
            s += v; sq += v * v;
        }
        float mean = s * (1.f / 64.f);
        float var  = sq * (1.f / 64.f) - mean * mean;
        smean[tid] = mean;
        srs[tid]   = rsqrtf(var + 1e-5f);
    }
    __syncthreads();
    {
        const int lt = tid >> 2;
        const int ck = (tid & 3) * 32;
        const int grp = ck >> 6;
        const float mean = smean[lt * 2 + grp];
        const float rs   = srs[lt * 2 + grp];
        float* o = out + (size_t)(t0 + lt) * CDIM + c0 + ck;
        const float* row = sf + lt * 132 + ck;
#pragma unroll
        for (int k = 0; k < 32; k += 4) {
            float4 w4 = *(const float4*)(wgt + c0 + ck + k);
            float4 b4 = *(const float4*)(bias + c0 + ck + k);
            float4 v  = make_float4(row[k], row[k + 1], row[k + 2], row[k + 3]);
            v.x = (v.x - mean) * rs * w4.x + b4.x;
            v.y = (v.y - mean) * rs * w4.y + b4.y;
            v.z = (v.z - mean) * rs * w4.z + b4.z;
            v.w = (v.w - mean) * rs * w4.w + b4.w;
            *(float4*)(o + k) = v;
        }
    }
}

// ---------------------------------------------------------------------------
extern "C" void kernel_launch(void* const* d_in, const int* in_sizes, int n_in,
                              void* d_out, int out_size)
{
    const float* X  = (const float*)d_in[0];
    const float* Wq = (const float*)d_in[1];
    const float* Wk = (const float*)d_in[2];
    const float* Wv = (const float*)d_in[3];
    const float* gw = (const float*)d_in[4];
    const float* gb = (const float*)d_in[5];
    float* out = (float*)d_out;

    prep_all<<<WB_BLOCKS + XB_BLOCKS, 256>>>(X, Wq, Wk, Wv);

    cudaFuncSetAttribute(proj_mma, cudaFuncAttributeMaxDynamicSharedMemorySize,
                         SMEM_PROJ);
    proj_mma<<<dim3(16, 64, 3), 256, SMEM_PROJ>>>();

    cudaFuncSetAttribute(qk_tv, cudaFuncAttributeMaxDynamicSharedMemorySize,
                         SMEM_QK);
    qk_tv<<<QK_BLOCKS + (CDIM / 64) * (TDIM / 64) * HN, 256, SMEM_QK>>>();

    cudaFuncSetAttribute(av_mma, cudaFuncAttributeMaxDynamicSharedMemorySize,
                         SMEM_AV);
    av_mma<<<dim3(8, NTIL), 256, SMEM_AV>>>(out, gw, gb);
}